// round 5
// baseline (speedup 1.0000x reference)
#include <cuda_runtime.h>
#include <stdint.h>
#include <math.h>

// DistanceTransformLoss: out = mean(BCEWithLogits(pred, tgt))
//                            + sqrt( sum(pred_bin*dist) / max(count,1) )  [0 if sum==0]
// dist[h] = min(|h - nearest target along H in column|, H) per (n,w) column.
// Shapes: (32,1,1024,1024) fp32.
//
// Single fused kernel. Block = 128 columns x full H, 256 threads.
// Warp g (0..7) streams rows [128g,128g+128); each lane owns 4 adjacent
// columns loaded as float4 (one LDG.128 per row per array, batched 4 rows
// deep for MLP). BCE accumulated inline; target/pred-sign bits packed into
// SMEM as per-column 1024-bit masks (padded [col][33] layout). Each thread
// then resolves the distance transform for its 4 columns' 128-bit segments.
// Last block (atomic ticket) reduces the 256 integer/double partials in a
// fixed order (deterministic) and writes the scalar.

#define NTHREADS 256
#define NBLOCKS  256           // 32 n * (1024/128) w-tiles
#define HH 1024
#define WW 1024
#define NWORDS 32              // 1024 bits / 32
#define PAD 33                 // bank-conflict-free [col][word] stride
#define BIG (1 << 20)

__device__ double       g_part_bce[NBLOCKS];
__device__ unsigned int g_part_tot[NBLOCKS];
__device__ unsigned int g_part_cnt[NBLOCKS];
__device__ unsigned int g_counter;   // zero-init; reset by electing block

__device__ __forceinline__ float bce_term(float p, float t) {
    return fmaxf(p, 0.f) - p * t + __logf(1.f + __expf(-fabsf(p)));
}

__global__ void __launch_bounds__(NTHREADS)
dtl_fused(const float* __restrict__ preds, const float* __restrict__ targs,
          float* __restrict__ out) {
    __shared__ uint32_t s_t[128 * PAD];
    __shared__ uint32_t s_p[128 * PAD];

    const int tid  = threadIdx.x;
    const int g    = tid >> 5;               // warp id = row segment 0..7
    const int lane = tid & 31;
    const int n    = blockIdx.x >> 3;        // 8 w-tiles per n
    const int w0   = (blockIdx.x & 7) << 7;  // * 128
    const int col0 = (lane << 2);            // 4 columns per lane (within tile)

    const long base = (long)n * (HH * WW) + (long)(g << 7) * WW + w0 + col0;

    float bce = 0.f;

    // ---- Pass 1: stream 128 rows (4 cols wide), BCE + bit packing ----
    #pragma unroll
    for (int w4 = 0; w4 < 4; ++w4) {         // 32-row chunk of this segment
        uint32_t tw0 = 0, tw1 = 0, tw2 = 0, tw3 = 0;
        uint32_t pw0 = 0, pw1 = 0, pw2 = 0, pw3 = 0;
        #pragma unroll
        for (int r8 = 0; r8 < 8; ++r8) {     // 4-row batches
            const long off = base + (long)((w4 << 5) + (r8 << 2)) * WW;
            float4 pa = __ldcs((const float4*)(preds + off));
            float4 pb = __ldcs((const float4*)(preds + off + WW));
            float4 pc = __ldcs((const float4*)(preds + off + 2 * WW));
            float4 pd = __ldcs((const float4*)(preds + off + 3 * WW));
            float4 ta = __ldcs((const float4*)(targs + off));
            float4 tb = __ldcs((const float4*)(targs + off + WW));
            float4 tc = __ldcs((const float4*)(targs + off + 2 * WW));
            float4 td = __ldcs((const float4*)(targs + off + 3 * WW));
            const int b0 = (r8 << 2);

            bce += bce_term(pa.x, ta.x) + bce_term(pa.y, ta.y)
                 + bce_term(pa.z, ta.z) + bce_term(pa.w, ta.w);
            if (ta.x > 0.5f) tw0 |= 1u << b0;       if (pa.x > 0.f) pw0 |= 1u << b0;
            if (ta.y > 0.5f) tw1 |= 1u << b0;       if (pa.y > 0.f) pw1 |= 1u << b0;
            if (ta.z > 0.5f) tw2 |= 1u << b0;       if (pa.z > 0.f) pw2 |= 1u << b0;
            if (ta.w > 0.5f) tw3 |= 1u << b0;       if (pa.w > 0.f) pw3 |= 1u << b0;

            bce += bce_term(pb.x, tb.x) + bce_term(pb.y, tb.y)
                 + bce_term(pb.z, tb.z) + bce_term(pb.w, tb.w);
            if (tb.x > 0.5f) tw0 |= 1u << (b0 + 1); if (pb.x > 0.f) pw0 |= 1u << (b0 + 1);
            if (tb.y > 0.5f) tw1 |= 1u << (b0 + 1); if (pb.y > 0.f) pw1 |= 1u << (b0 + 1);
            if (tb.z > 0.5f) tw2 |= 1u << (b0 + 1); if (pb.z > 0.f) pw2 |= 1u << (b0 + 1);
            if (tb.w > 0.5f) tw3 |= 1u << (b0 + 1); if (pb.w > 0.f) pw3 |= 1u << (b0 + 1);

            bce += bce_term(pc.x, tc.x) + bce_term(pc.y, tc.y)
                 + bce_term(pc.z, tc.z) + bce_term(pc.w, tc.w);
            if (tc.x > 0.5f) tw0 |= 1u << (b0 + 2); if (pc.x > 0.f) pw0 |= 1u << (b0 + 2);
            if (tc.y > 0.5f) tw1 |= 1u << (b0 + 2); if (pc.y > 0.f) pw1 |= 1u << (b0 + 2);
            if (tc.z > 0.5f) tw2 |= 1u << (b0 + 2); if (pc.z > 0.f) pw2 |= 1u << (b0 + 2);
            if (tc.w > 0.5f) tw3 |= 1u << (b0 + 2); if (pc.w > 0.f) pw3 |= 1u << (b0 + 2);

            bce += bce_term(pd.x, td.x) + bce_term(pd.y, td.y)
                 + bce_term(pd.z, td.z) + bce_term(pd.w, td.w);
            if (td.x > 0.5f) tw0 |= 1u << (b0 + 3); if (pd.x > 0.f) pw0 |= 1u << (b0 + 3);
            if (td.y > 0.5f) tw1 |= 1u << (b0 + 3); if (pd.y > 0.f) pw1 |= 1u << (b0 + 3);
            if (td.z > 0.5f) tw2 |= 1u << (b0 + 3); if (pd.z > 0.f) pw2 |= 1u << (b0 + 3);
            if (td.w > 0.5f) tw3 |= 1u << (b0 + 3); if (pd.w > 0.f) pw3 |= 1u << (b0 + 3);
        }
        const int word = (g << 2) + w4;
        s_t[(col0 + 0) * PAD + word] = tw0;  s_p[(col0 + 0) * PAD + word] = pw0;
        s_t[(col0 + 1) * PAD + word] = tw1;  s_p[(col0 + 1) * PAD + word] = pw1;
        s_t[(col0 + 2) * PAD + word] = tw2;  s_p[(col0 + 2) * PAD + word] = pw2;
        s_t[(col0 + 3) * PAD + word] = tw3;  s_p[(col0 + 3) * PAD + word] = pw3;
    }
    __syncthreads();

    // ---- Pass 2: distance transform for 4 columns x own 128-bit segment ----
    const int w4base = g << 2;
    uint32_t tot = 0u, cnt = 0u;

    #pragma unroll
    for (int j = 0; j < 4; ++j) {
        const uint32_t* stc = s_t + (col0 + j) * PAD;
        const uint32_t* spc = s_p + (col0 + j) * PAD;

        int lt = -BIG;                        // last target before segment
        for (int w = w4base - 1; w >= 0; --w) {
            uint32_t v = stc[w];
            if (v) { lt = (w << 5) + 31 - __clz(v); break; }
        }
        int scanw = w4base;                   // next-target iterator
        uint32_t curm = stc[scanw];
        int nt;
        while (curm == 0u && scanw < NWORDS - 1) { ++scanw; curm = stc[scanw]; }
        if (curm) { nt = (scanw << 5) + __ffs(curm) - 1; curm &= curm - 1u; }
        else        nt = BIG;

        #pragma unroll
        for (int w4 = 0; w4 < 4; ++w4) {
            uint32_t tw = stc[w4base + w4];
            uint32_t pw = spc[w4base + w4];
            int hbase = (w4base + w4) << 5;
            #pragma unroll 4
            for (int b = 0; b < 32; ++b) {
                int h = hbase + b;
                if ((tw >> b) & 1u) {
                    lt = h;
                    while (curm == 0u && scanw < NWORDS - 1) { ++scanw; curm = stc[scanw]; }
                    if (curm) { nt = (scanw << 5) + __ffs(curm) - 1; curm &= curm - 1u; }
                    else        nt = BIG;
                } else if ((pw >> b) & 1u) {
                    tot += (uint32_t)min(min(h - lt, nt - h), HH);
                    cnt += 1u;
                }
            }
        }
    }

    // ---- Block reduction -> fixed per-block slots (deterministic) ----
    const unsigned fullm = 0xFFFFFFFFu;
    for (int off = 16; off; off >>= 1) {
        bce += __shfl_down_sync(fullm, bce, off);
        tot += __shfl_down_sync(fullm, tot, off);
        cnt += __shfl_down_sync(fullm, cnt, off);
    }
    __shared__ float    rb[8];
    __shared__ uint32_t rt[8], rc[8];
    if (lane == 0) { rb[g] = bce; rt[g] = tot; rc[g] = cnt; }
    __syncthreads();
    __shared__ int s_last;
    if (tid == 0) {
        float    b2 = 0.f;
        uint32_t t2 = 0u, c2 = 0u;
        #pragma unroll
        for (int i = 0; i < 8; ++i) { b2 += rb[i]; t2 += rt[i]; c2 += rc[i]; }
        g_part_bce[blockIdx.x] = (double)b2;
        g_part_tot[blockIdx.x] = t2;
        g_part_cnt[blockIdx.x] = c2;
        __threadfence();
        unsigned old = atomicAdd(&g_counter, 1u);
        s_last = (old == NBLOCKS - 1);
    }
    __syncthreads();

    // ---- Last block: deterministic final reduction + scalar write ----
    if (s_last) {
        __shared__ double             fb[NTHREADS];
        __shared__ unsigned long long ft[NTHREADS], fc[NTHREADS];
        fb[tid] = g_part_bce[tid];            // NBLOCKS == NTHREADS == 256
        ft[tid] = (unsigned long long)g_part_tot[tid];
        fc[tid] = (unsigned long long)g_part_cnt[tid];
        __syncthreads();
        for (int s = NTHREADS / 2; s; s >>= 1) {
            if (tid < s) { fb[tid] += fb[tid + s]; ft[tid] += ft[tid + s]; fc[tid] += fc[tid + s]; }
            __syncthreads();
        }
        if (tid == 0) {
            double bce_mean = fb[0] / 33554432.0;     // 32*1024*1024
            double totd = (double)ft[0];
            double cntd = (double)fc[0];
            double border = (ft[0] == 0ull) ? 0.0 : totd / (cntd < 1.0 ? 1.0 : cntd);
            out[0] = (float)(bce_mean + sqrt(border));
            g_counter = 0u;                  // reset for next graph replay
        }
    }
}

extern "C" void kernel_launch(void* const* d_in, const int* in_sizes, int n_in,
                              void* d_out, int out_size) {
    const float* preds = (const float*)d_in[0];
    const float* targs = (const float*)d_in[1];
    dtl_fused<<<NBLOCKS, NTHREADS>>>(preds, targs, (float*)d_out);
}